// round 2
// baseline (speedup 1.0000x reference)
#include <cuda_runtime.h>
#include <cuda_bf16.h>
#include <math.h>

#define NB 65536
#define LH 64
#define GOALC 0.5f
#define MINPC (-1.2f)
#define UTHRESH 0.5f

// XLA / Eigen rational tanh approximation for f32 (generic_fast_tanh_float).
// Both XLA:CPU (Eigen) and XLA:GPU lower jnp.tanh(f32) to this rational form.
__device__ __forceinline__ float xla_tanh(float xin) {
    const float x = fminf(fmaxf(xin, -7.99881172180175781f), 7.99881172180175781f);
    const float x2 = __fmul_rn(x, x);
    float p = __fmaf_rn(x2, -2.76076847742355e-16f, 2.00018790482477e-13f);
    p = __fmaf_rn(x2, p, -8.60467152213735e-11f);
    p = __fmaf_rn(x2, p, 5.12229709037114e-08f);
    p = __fmaf_rn(x2, p, 1.48572235717979e-05f);
    p = __fmaf_rn(x2, p, 6.37261928875436e-04f);
    p = __fmaf_rn(x2, p, 4.89352455891786e-03f);
    p = __fmul_rn(x, p);
    float q = __fmaf_rn(x2, 1.19825839466702e-06f, 1.18534705686654e-04f);
    q = __fmaf_rn(x2, q, 2.26843463243900e-03f);
    q = __fmaf_rn(x2, q, 4.89352518554385e-03f);
    const float r = __fdiv_rn(p, q);
    return (fabsf(xin) < 0.0004f) ? xin : r;
}

__global__ __launch_bounds__(256, 8)
void mc_kernel(const float4* __restrict__ x,
               const float* __restrict__ W1,
               const float* __restrict__ b1,
               const float* __restrict__ W2,
               const float* __restrict__ b2,
               const int* __restrict__ n_steps,
               float4* __restrict__ out)
{
    // Pack weights per hidden unit: {W1[0][j], W1[1][j], b1[j], W2[j]}
    __shared__ float4 w[LH];
    const int tid = threadIdx.x;
    if (tid < LH) {
        w[tid] = make_float4(W1[tid], W1[LH + tid], b1[tid], W2[tid]);
    }
    __syncthreads();

    const float bias2 = b2[0];
    const int n = n_steps ? n_steps[0] : 64;

    const int i = blockIdx.x * blockDim.x + tid;
    float4 s = x[i];
    float p = s.x, v = s.y, u = s.z, a = s.w;

    for (int t = 0; t < n; ++t) {
        // active = p <= GOAL; once false it stays false forever -> break is exact
        if (p > GOALC) break;

        const bool reset = (p <= MINPC);
        const float pr = reset ? MINPC : p;
        const float vr = reset ? 0.0f : v;

        // Layer 1: (p*W1[0j] then fma v*W1[1j]) + b1 as a SEPARATE rounded add,
        // then relu. Matches gemm followed by bias-add fusion.
        // Layer 2: fma-Kahan compensated dot -> ~truth, then separate +b2.
        float acc = 0.0f, comp = 0.0f;
        #pragma unroll
        for (int j = 0; j < LH; ++j) {
            const float4 ww = w[j];
            const float dot2 = __fmaf_rn(vr, ww.y, __fmul_rn(pr, ww.x));
            const float h = fmaxf(__fadd_rn(dot2, ww.z), 0.0f);
            const float y  = __fmaf_rn(h, ww.w, -comp);   // term with compensation folded in
            const float tn = __fadd_rn(acc, y);
            comp = __fsub_rn(__fsub_rn(tn, acc), y);
            acc = tn;
        }
        const float pre = __fadd_rn(acc, bias2);

        const float an = xla_tanh(pre);
        const float un = (an <= UTHRESH) ? -1.0f : 1.0f;

        // vn = vr + un*0.0015 - 0.0025*cos(3*pr), each op rounded separately
        const float arg = __fmul_rn(3.0f, pr);
        const float c   = (float)cos((double)arg);   // correctly-rounded f32 cos
        const float m1  = __fmul_rn(un, 0.0015f);
        const float s1  = __fadd_rn(vr, m1);
        const float m2  = __fmul_rn(0.0025f, c);
        const float vn  = __fsub_rn(s1, m2);
        const float pn  = __fadd_rn(pr, vn);

        p = pn; v = vn; u = un; a = an;
    }

    out[i] = make_float4(p, v, u, a);
}

extern "C" void kernel_launch(void* const* d_in, const int* in_sizes, int n_in,
                              void* d_out, int out_size) {
    const float* x  = (const float*)d_in[0];
    const float* W1 = (const float*)d_in[1];
    const float* b1 = (const float*)d_in[2];
    const float* W2 = (const float*)d_in[3];
    const float* b2 = (const float*)d_in[4];
    const int* ns   = (n_in >= 6) ? (const int*)d_in[5] : nullptr;

    mc_kernel<<<NB / 256, 256>>>((const float4*)x, W1, b1, W2, b2, ns,
                                 (float4*)d_out);
}

// round 3
// speedup vs baseline: 2.0744x; 2.0744x over previous
#include <cuda_runtime.h>
#include <cuda_bf16.h>
#include <math.h>

#define NB 65536
#define LH 64
#define GOALC 0.5f
#define MINPC (-1.2f)
#define UTHRESH 0.5f

// XLA / Eigen rational tanh approximation for f32 (matches reference lowering).
__device__ __forceinline__ float xla_tanh(float xin) {
    const float x = fminf(fmaxf(xin, -7.99881172180175781f), 7.99881172180175781f);
    const float x2 = __fmul_rn(x, x);
    float p = __fmaf_rn(x2, -2.76076847742355e-16f, 2.00018790482477e-13f);
    p = __fmaf_rn(x2, p, -8.60467152213735e-11f);
    p = __fmaf_rn(x2, p, 5.12229709037114e-08f);
    p = __fmaf_rn(x2, p, 1.48572235717979e-05f);
    p = __fmaf_rn(x2, p, 6.37261928875436e-04f);
    p = __fmaf_rn(x2, p, 4.89352455891786e-03f);
    p = __fmul_rn(x, p);
    float q = __fmaf_rn(x2, 1.19825839466702e-06f, 1.18534705686654e-04f);
    q = __fmaf_rn(x2, q, 2.26843463243900e-03f);
    q = __fmaf_rn(x2, q, 4.89352518554385e-03f);
    const float r = __fdiv_rn(p, q);
    return (fabsf(xin) < 0.0004f) ? xin : r;
}

// fp32 cos for |x| <= ~3.8, ~1-1.5 ulp: Cody-Waite reduction keeping the
// residual rl, then poly with first-order correction. Avoids the fp64 pipe.
__device__ __forceinline__ float cos_cw(float x) {
    const float kf = rintf(__fmul_rn(x, 0.63661977236758134f)); // x * 2/pi
    const int k = (int)kf;
    // pi/2 split: DP1 exact in 7 bits, DP2 ~11 bits -> kf*DPi exact for |k|<=2
    const float DP1 = 1.5703125f;
    const float DP2 = 4.837512969970703125e-4f;
    const float DP3 = 7.549789948768648e-8f;
    const float t  = __fmaf_rn(-kf, DP1, x);          // exact (Sterbenz)
    const float rh = __fmaf_rn(-kf, DP2, t);
    // residual of the second subtraction + third constant word
    float rl = __fsub_rn(__fsub_rn(t, rh), __fmul_rn(kf, DP2));
    rl = __fmaf_rn(-kf, DP3, rl);
    const float z = __fmul_rn(rh, rh);

    // cos poly on [-pi/4, pi/4] with -rl*sin(r) ~= -rl*rh correction
    float pc = __fmaf_rn(z, 2.443315711809948e-5f, -1.388731625493765e-3f);
    pc = __fmaf_rn(z, pc, 4.166664568298827e-2f);
    float c = __fmaf_rn(z, -0.5f, 1.0f);
    c = __fmaf_rn(__fmul_rn(z, z), pc, c);
    c = __fmaf_rn(-rl, rh, c);

    // sin poly with +rl*cos(r) ~= +rl correction
    float ps = __fmaf_rn(z, -1.9515295891e-4f, 8.3321608736e-3f);
    ps = __fmaf_rn(z, ps, -1.6666654611e-1f);
    float s = __fmaf_rn(__fmul_rn(rh, z), ps, rl);
    s = __fadd_rn(rh, s);

    const int q = k & 3;   // cos(x) = {cos, -sin, -cos, sin}[q](r)
    float r = (q & 1) ? s : c;
    if (q == 1 || q == 2) r = -r;
    return r;
}

__device__ __forceinline__ void two_sum(float a, float b, float& s, float& e) {
    s = __fadd_rn(a, b);
    const float bb = __fsub_rn(s, a);
    e = __fadd_rn(__fsub_rn(a, __fsub_rn(s, bb)), __fsub_rn(b, bb));
}

template<bool B1_ZERO>
__device__ __forceinline__ void run_agent(
    const float4* __restrict__ w, float bias2, int n,
    float& p, float& v, float& u, float& a)
{
    for (int t = 0; t < n; ++t) {
        if (p > GOALC) break;   // inactive is absorbing -> break is exact

        const bool reset = (p <= MINPC);
        const float pr = reset ? MINPC : p;
        const float vr = reset ? 0.0f : v;

        // 4 independent Kahan lanes over the 64 hidden units
        float acc0 = 0.f, acc1 = 0.f, acc2 = 0.f, acc3 = 0.f;
        float cp0 = 0.f, cp1 = 0.f, cp2 = 0.f, cp3 = 0.f;
        #pragma unroll
        for (int j = 0; j < LH; j += 4) {
            #pragma unroll
            for (int l = 0; l < 4; ++l) {
                const float4 ww = w[j + l];
                float d = __fmaf_rn(vr, ww.y, __fmul_rn(pr, ww.x));
                if (!B1_ZERO) d = __fadd_rn(d, ww.z);
                const float h = fmaxf(d, 0.0f);
                float& acc = (l == 0) ? acc0 : (l == 1) ? acc1 : (l == 2) ? acc2 : acc3;
                float& cp  = (l == 0) ? cp0  : (l == 1) ? cp1  : (l == 2) ? cp2  : cp3;
                const float y  = __fmaf_rn(h, ww.w, -cp);
                const float tn = __fadd_rn(acc, y);
                cp = __fsub_rn(__fsub_rn(tn, acc), y);
                acc = tn;
            }
        }
        // exact merge of the 4 compensated partials
        float s1, e1, s2, e2, s3, e3;
        two_sum(acc0, acc1, s1, e1);
        two_sum(acc2, acc3, s2, e2);
        two_sum(s1, s2, s3, e3);
        const float csum = __fadd_rn(__fadd_rn(cp0, cp1), __fadd_rn(cp2, cp3));
        const float err = __fsub_rn(__fadd_rn(__fadd_rn(e1, e2), e3), csum);
        const float dot = __fadd_rn(s3, err);
        const float pre = __fadd_rn(dot, bias2);

        const float an = xla_tanh(pre);
        const float un = (an <= UTHRESH) ? -1.0f : 1.0f;

        const float c  = cos_cw(__fmul_rn(3.0f, pr));
        const float vn = __fsub_rn(__fadd_rn(vr, __fmul_rn(un, 0.0015f)),
                                   __fmul_rn(0.0025f, c));
        const float pn = __fadd_rn(pr, vn);

        p = pn; v = vn; u = un; a = an;
    }
}

__global__ __launch_bounds__(256, 2)
void mc_kernel(const float4* __restrict__ x,
               const float* __restrict__ W1,
               const float* __restrict__ b1,
               const float* __restrict__ W2,
               const float* __restrict__ b2,
               const int* __restrict__ n_steps,
               float4* __restrict__ out)
{
    __shared__ float4 w[LH];
    const int tid = threadIdx.x;
    int zok = 1;
    if (tid < LH) {
        const float b1v = b1[tid];
        w[tid] = make_float4(W1[tid], W1[LH + tid], b1v, W2[tid]);
        zok = (__float_as_uint(b1v) == 0u);
    }
    const int b1_zero = __syncthreads_and(zok);

    const float bias2 = b2[0];
    const int n = n_steps ? n_steps[0] : 64;

    const int i = blockIdx.x * blockDim.x + tid;
    const float4 s = x[i];
    float p = s.x, v = s.y, u = s.z, a = s.w;

    if (b1_zero) run_agent<true >(w, bias2, n, p, v, u, a);
    else         run_agent<false>(w, bias2, n, p, v, u, a);

    out[i] = make_float4(p, v, u, a);
}

extern "C" void kernel_launch(void* const* d_in, const int* in_sizes, int n_in,
                              void* d_out, int out_size) {
    const float* x  = (const float*)d_in[0];
    const float* W1 = (const float*)d_in[1];
    const float* b1 = (const float*)d_in[2];
    const float* W2 = (const float*)d_in[3];
    const float* b2 = (const float*)d_in[4];
    const int* ns   = (n_in >= 6) ? (const int*)d_in[5] : nullptr;

    mc_kernel<<<NB / 256, 256>>>((const float4*)x, W1, b1, W2, b2, ns,
                                 (float4*)d_out);
}

// round 4
// speedup vs baseline: 2.8238x; 1.3612x over previous
#include <cuda_runtime.h>
#include <cuda_bf16.h>
#include <math.h>

#define NB 65536
#define HALF 32768
#define LH 64
#define GOALC 0.5f
#define MINPC (-1.2f)
#define UTHRESH 0.5f

// XLA / Eigen rational tanh approximation for f32 (matches reference lowering).
__device__ __forceinline__ float xla_tanh(float xin) {
    const float x = fminf(fmaxf(xin, -7.99881172180175781f), 7.99881172180175781f);
    const float x2 = __fmul_rn(x, x);
    float p = __fmaf_rn(x2, -2.76076847742355e-16f, 2.00018790482477e-13f);
    p = __fmaf_rn(x2, p, -8.60467152213735e-11f);
    p = __fmaf_rn(x2, p, 5.12229709037114e-08f);
    p = __fmaf_rn(x2, p, 1.48572235717979e-05f);
    p = __fmaf_rn(x2, p, 6.37261928875436e-04f);
    p = __fmaf_rn(x2, p, 4.89352455891786e-03f);
    p = __fmul_rn(x, p);
    float q = __fmaf_rn(x2, 1.19825839466702e-06f, 1.18534705686654e-04f);
    q = __fmaf_rn(x2, q, 2.26843463243900e-03f);
    q = __fmaf_rn(x2, q, 4.89352518554385e-03f);
    const float r = __fdiv_rn(p, q);
    return (fabsf(xin) < 0.0004f) ? xin : r;
}

// fp32 cos (|x| <= ~3.8), Cody-Waite with residual carry, ~1-1.5 ulp.
__device__ __forceinline__ float cos_cw(float x) {
    const float kf = rintf(__fmul_rn(x, 0.63661977236758134f));
    const int k = (int)kf;
    const float DP1 = 1.5703125f;
    const float DP2 = 4.837512969970703125e-4f;
    const float DP3 = 7.549789948768648e-8f;
    const float t  = __fmaf_rn(-kf, DP1, x);
    const float rh = __fmaf_rn(-kf, DP2, t);
    float rl = __fsub_rn(__fsub_rn(t, rh), __fmul_rn(kf, DP2));
    rl = __fmaf_rn(-kf, DP3, rl);
    const float z = __fmul_rn(rh, rh);

    float pc = __fmaf_rn(z, 2.443315711809948e-5f, -1.388731625493765e-3f);
    pc = __fmaf_rn(z, pc, 4.166664568298827e-2f);
    float c = __fmaf_rn(z, -0.5f, 1.0f);
    c = __fmaf_rn(__fmul_rn(z, z), pc, c);
    c = __fmaf_rn(-rl, rh, c);

    float ps = __fmaf_rn(z, -1.9515295891e-4f, 8.3321608736e-3f);
    ps = __fmaf_rn(z, ps, -1.6666654611e-1f);
    float s = __fmaf_rn(__fmul_rn(rh, z), ps, rl);
    s = __fadd_rn(rh, s);

    const int q = k & 3;
    float r = (q & 1) ? s : c;
    if (q == 1 || q == 2) r = -r;
    return r;
}

__device__ __forceinline__ void two_sum(float a, float b, float& s, float& e) {
    s = __fadd_rn(a, b);
    const float bb = __fsub_rn(s, a);
    e = __fadd_rn(__fsub_rn(a, __fsub_rn(s, bb)), __fsub_rn(b, bb));
}

// One full step for one agent. Math sequence identical to R3 (bit-exact).
__device__ __forceinline__ void step_agent(
    const float4* __restrict__ w, float bias2,
    float& p, float& v, float& u, float& a)
{
    const bool reset = (p <= MINPC);
    const float pr = reset ? MINPC : p;
    const float vr = reset ? 0.0f : v;

    float acc0 = 0.f, acc1 = 0.f, acc2 = 0.f, acc3 = 0.f;
    float cp0 = 0.f, cp1 = 0.f, cp2 = 0.f, cp3 = 0.f;
    #pragma unroll
    for (int j = 0; j < LH; j += 4) {
        #pragma unroll
        for (int l = 0; l < 4; ++l) {
            const float4 ww = w[j + l];
            const float d = __fmaf_rn(vr, ww.y, __fmul_rn(pr, ww.x));
            const float h = fmaxf(d, 0.0f);   // b1 == 0 verified by caller
            float& acc = (l == 0) ? acc0 : (l == 1) ? acc1 : (l == 2) ? acc2 : acc3;
            float& cp  = (l == 0) ? cp0  : (l == 1) ? cp1  : (l == 2) ? cp2  : cp3;
            const float y  = __fmaf_rn(h, ww.w, -cp);
            const float tn = __fadd_rn(acc, y);
            cp = __fsub_rn(__fsub_rn(tn, acc), y);
            acc = tn;
        }
    }
    float s1, e1, s2, e2, s3, e3;
    two_sum(acc0, acc1, s1, e1);
    two_sum(acc2, acc3, s2, e2);
    two_sum(s1, s2, s3, e3);
    const float csum = __fadd_rn(__fadd_rn(cp0, cp1), __fadd_rn(cp2, cp3));
    const float err = __fsub_rn(__fadd_rn(__fadd_rn(e1, e2), e3), csum);
    const float dot = __fadd_rn(s3, err);
    const float pre = __fadd_rn(dot, bias2);

    const float an = xla_tanh(pre);
    const float un = (an <= UTHRESH) ? -1.0f : 1.0f;

    const float c  = cos_cw(__fmul_rn(3.0f, pr));
    const float vn = __fsub_rn(__fadd_rn(vr, __fmul_rn(un, 0.0015f)),
                               __fmul_rn(0.0025f, c));
    const float pn = __fadd_rn(pr, vn);

    p = pn; v = vn; u = un; a = an;
}

// Fallback: b1 != 0 (adds the bias like R3's non-zero path).
__device__ __forceinline__ void step_agent_b1(
    const float4* __restrict__ w, float bias2,
    float& p, float& v, float& u, float& a)
{
    const bool reset = (p <= MINPC);
    const float pr = reset ? MINPC : p;
    const float vr = reset ? 0.0f : v;

    float acc0 = 0.f, acc1 = 0.f, acc2 = 0.f, acc3 = 0.f;
    float cp0 = 0.f, cp1 = 0.f, cp2 = 0.f, cp3 = 0.f;
    #pragma unroll
    for (int j = 0; j < LH; j += 4) {
        #pragma unroll
        for (int l = 0; l < 4; ++l) {
            const float4 ww = w[j + l];
            float d = __fmaf_rn(vr, ww.y, __fmul_rn(pr, ww.x));
            d = __fadd_rn(d, ww.z);
            const float h = fmaxf(d, 0.0f);
            float& acc = (l == 0) ? acc0 : (l == 1) ? acc1 : (l == 2) ? acc2 : acc3;
            float& cp  = (l == 0) ? cp0  : (l == 1) ? cp1  : (l == 2) ? cp2  : cp3;
            const float y  = __fmaf_rn(h, ww.w, -cp);
            const float tn = __fadd_rn(acc, y);
            cp = __fsub_rn(__fsub_rn(tn, acc), y);
            acc = tn;
        }
    }
    float s1, e1, s2, e2, s3, e3;
    two_sum(acc0, acc1, s1, e1);
    two_sum(acc2, acc3, s2, e2);
    two_sum(s1, s2, s3, e3);
    const float csum = __fadd_rn(__fadd_rn(cp0, cp1), __fadd_rn(cp2, cp3));
    const float err = __fsub_rn(__fadd_rn(__fadd_rn(e1, e2), e3), csum);
    const float dot = __fadd_rn(s3, err);
    const float pre = __fadd_rn(dot, bias2);

    const float an = xla_tanh(pre);
    const float un = (an <= UTHRESH) ? -1.0f : 1.0f;

    const float c  = cos_cw(__fmul_rn(3.0f, pr));
    const float vn = __fsub_rn(__fadd_rn(vr, __fmul_rn(un, 0.0015f)),
                               __fmul_rn(0.0025f, c));
    const float pn = __fadd_rn(pr, vn);

    p = pn; v = vn; u = un; a = an;
}

__global__ __launch_bounds__(64)
void mc_kernel(const float4* __restrict__ x,
               const float* __restrict__ W1,
               const float* __restrict__ b1,
               const float* __restrict__ W2,
               const float* __restrict__ b2,
               const int* __restrict__ n_steps,
               float4* __restrict__ out)
{
    __shared__ float4 w[LH];
    const int tid = threadIdx.x;
    const float b1v = b1[tid];
    w[tid] = make_float4(W1[tid], W1[LH + tid], b1v, W2[tid]);
    const int b1_zero = __syncthreads_and(__float_as_uint(b1v) == 0u);

    const float bias2 = b2[0];
    const int n = n_steps ? n_steps[0] : 64;

    const int iA = blockIdx.x * blockDim.x + tid;   // agents [0, 32768)
    const int iB = iA + HALF;                       // agents [32768, 65536)

    const float4 sA = x[iA];
    const float4 sB = x[iB];
    float pA = sA.x, vA = sA.y, uA = sA.z, aA = sA.w;
    float pB = sB.x, vB = sB.y, uB = sB.z, aB = sB.w;

    if (b1_zero) {
        for (int t = 0; t < n; ++t) {
            const bool actA = (pA <= GOALC);
            const bool actB = (pB <= GOALC);
            if (!(actA || actB)) break;
            if (actA) step_agent(w, bias2, pA, vA, uA, aA);
            if (actB) step_agent(w, bias2, pB, vB, uB, aB);
        }
    } else {
        for (int t = 0; t < n; ++t) {
            const bool actA = (pA <= GOALC);
            const bool actB = (pB <= GOALC);
            if (!(actA || actB)) break;
            if (actA) step_agent_b1(w, bias2, pA, vA, uA, aA);
            if (actB) step_agent_b1(w, bias2, pB, vB, uB, aB);
        }
    }

    out[iA] = make_float4(pA, vA, uA, aA);
    out[iB] = make_float4(pB, vB, uB, aB);
}

extern "C" void kernel_launch(void* const* d_in, const int* in_sizes, int n_in,
                              void* d_out, int out_size) {
    const float* x  = (const float*)d_in[0];
    const float* W1 = (const float*)d_in[1];
    const float* b1 = (const float*)d_in[2];
    const float* W2 = (const float*)d_in[3];
    const float* b2 = (const float*)d_in[4];
    const int* ns   = (n_in >= 6) ? (const int*)d_in[5] : nullptr;

    mc_kernel<<<HALF / 64, 64>>>((const float4*)x, W1, b1, W2, b2, ns,
                                 (float4*)d_out);
}